// round 3
// baseline (speedup 1.0000x reference)
#include <cuda_runtime.h>
#include <cuda_fp16.h>
#include <cstdint>

#define D 128
#define NMAX 100000

// Scratch (device globals -- no allocation allowed):
__device__ __half g_hWh[(size_t)NMAX * D];     // hW = h @ W^T in fp16
__device__ int    g_rowptr[NMAX + 1];

// ---------------------------------------------------------------------------
// mma.sync m16n8k16 fp16 -> fp32
// ---------------------------------------------------------------------------
__device__ __forceinline__ void mma16816(float4& c,
                                         uint32_t a0, uint32_t a1, uint32_t a2, uint32_t a3,
                                         uint32_t b0, uint32_t b1)
{
    asm volatile(
        "mma.sync.aligned.m16n8k16.row.col.f32.f16.f16.f32 "
        "{%0,%1,%2,%3}, {%4,%5,%6,%7}, {%8,%9}, {%0,%1,%2,%3};\n"
        : "+f"(c.x), "+f"(c.y), "+f"(c.z), "+f"(c.w)
        : "r"(a0), "r"(a1), "r"(a2), "r"(a3), "r"(b0), "r"(b1));
}

// ---------------------------------------------------------------------------
// Kernel 1: hW[i][j] = sum_k h[i][k] * W[j][k] via mma (fp16 in, fp32 acc).
// W converted fp32->fp16 on the fly during the B-tile load.
// Block: 256 threads (8 warps). Tile: 128 rows x 128 cols, K chunked by 64.
// ---------------------------------------------------------------------------
#define KC 64
#define KPAD 72

__global__ __launch_bounds__(256) void gemm_hwt_fp16_kernel(
    const float* __restrict__ h,
    const float* __restrict__ W,
    int N)
{
    __shared__ __half Asm[128][KPAD];
    __shared__ __half Bsm[128][KPAD];

    const int t    = threadIdx.x;
    const int lane = t & 31;
    const int warp = t >> 5;
    const int m0   = blockIdx.x * 128;

    const int qr = lane >> 2;
    const int qc = (lane & 3) * 2;
    const int mrow = warp * 16 + qr;

    float4 acc[16];
#pragma unroll
    for (int j = 0; j < 16; j++) acc[j] = make_float4(0.f, 0.f, 0.f, 0.f);

    for (int kc = 0; kc < 2; kc++) {
        // ---- load A chunk: 128 rows x 64 k, fp32 -> fp16, guarded ----
#pragma unroll
        for (int it = 0; it < 8; it++) {
            int idx = t + it * 256;
            int row = idx >> 4;
            int q   = idx & 15;
            int gr  = m0 + row;
            float4 v = make_float4(0.f, 0.f, 0.f, 0.f);
            if (gr < N)
                v = reinterpret_cast<const float4*>(h + (size_t)gr * D + kc * KC)[q];
            __half2* dst = reinterpret_cast<__half2*>(&Asm[row][q * 4]);
            dst[0] = __floats2half2_rn(v.x, v.y);
            dst[1] = __floats2half2_rn(v.z, v.w);
        }
        // ---- load B chunk: W[j][kc*64 + ...] fp32 -> fp16 ----
#pragma unroll
        for (int it = 0; it < 8; it++) {
            int idx = t + it * 256;
            int row = idx >> 4;      // j
            int q   = idx & 15;
            float4 v = reinterpret_cast<const float4*>(W + (size_t)row * D + kc * KC)[q];
            __half2* dst = reinterpret_cast<__half2*>(&Bsm[row][q * 4]);
            dst[0] = __floats2half2_rn(v.x, v.y);
            dst[1] = __floats2half2_rn(v.z, v.w);
        }
        __syncthreads();

        uint32_t a[4][4];
#pragma unroll
        for (int ks = 0; ks < 4; ks++) {
            int kk = ks * 16;
            a[ks][0] = *reinterpret_cast<const uint32_t*>(&Asm[mrow][kk + qc]);
            a[ks][1] = *reinterpret_cast<const uint32_t*>(&Asm[mrow + 8][kk + qc]);
            a[ks][2] = *reinterpret_cast<const uint32_t*>(&Asm[mrow][kk + 8 + qc]);
            a[ks][3] = *reinterpret_cast<const uint32_t*>(&Asm[mrow + 8][kk + 8 + qc]);
        }

#pragma unroll
        for (int j = 0; j < 16; j++) {
            int n0 = j * 8;
            const __half* brow = &Bsm[n0 + qr][0];
#pragma unroll
            for (int ks = 0; ks < 4; ks++) {
                int kk = ks * 16;
                uint32_t b0 = *reinterpret_cast<const uint32_t*>(brow + kk + qc);
                uint32_t b1 = *reinterpret_cast<const uint32_t*>(brow + kk + 8 + qc);
                mma16816(acc[j], a[ks][0], a[ks][1], a[ks][2], a[ks][3], b0, b1);
            }
        }
        __syncthreads();
    }

    const int r0 = m0 + mrow;
    const int r1 = r0 + 8;
#pragma unroll
    for (int j = 0; j < 16; j++) {
        int col = j * 8 + qc;
        if (r0 < N)
            *reinterpret_cast<__half2*>(&g_hWh[(size_t)r0 * D + col]) =
                __floats2half2_rn(acc[j].x, acc[j].y);
        if (r1 < N)
            *reinterpret_cast<__half2*>(&g_hWh[(size_t)r1 * D + col]) =
                __floats2half2_rn(acc[j].z, acc[j].w);
    }
}

// ---------------------------------------------------------------------------
// Kernel 2: build CSR row pointers from sorted edge_rows. O(E) scatter.
// ---------------------------------------------------------------------------
__global__ __launch_bounds__(256) void build_rowptr_kernel(
    const int* __restrict__ rows, int E, int N)
{
    int e = blockIdx.x * blockDim.x + threadIdx.x;
    if (e >= E) return;
    int r     = rows[e];
    int rprev = (e == 0) ? -1 : rows[e - 1];
    for (int i = rprev + 1; i <= r; i++) g_rowptr[i] = e;
    if (e == E - 1) {
        for (int i = r + 1; i <= N; i++) g_rowptr[i] = E;
    }
}

// ---------------------------------------------------------------------------
// Kernel 3: Tensor-core SpMM. One warp per 8 consecutive nodes.
// Per 16-edge chunk:  C[128 dims x 8 nodes] += A(gathered hW rows, fp16,
// via cp.async->smem->ldmatrix.trans) @ B(masked edge values, built in regs).
// Then bias + ReLU epilogue through a smem transpose.
// ---------------------------------------------------------------------------
#define STAGE_STRIDE 272              // 256B row + 16B pad (bank-conflict-free)
#define WARPS_PER_BLOCK 8

__global__ __launch_bounds__(256) void spmm_tc_kernel(
    const int*   __restrict__ rows,
    const int*   __restrict__ cols,
    const float* __restrict__ vals,
    const float* __restrict__ b,
    float*       __restrict__ out,
    int N)
{
    __shared__ char  stage_raw[WARPS_PER_BLOCK * 16 * STAGE_STRIDE];
    __shared__ float4 bsm4[32];

    const int t    = threadIdx.x;
    const int lane = t & 31;
    const int warp = t >> 5;

    if (t < 32) bsm4[t] = reinterpret_cast<const float4*>(b)[t];
    __syncthreads();

    const int gw = blockIdx.x * WARPS_PER_BLOCK + warp;  // node-group id
    const int n0 = gw * 8;
    if (n0 >= N) return;
    const int nodeEnd = min(8, N - n0);

    char* stage = stage_raw + warp * 16 * STAGE_STRIDE;
    const uint32_t stageAddr = (uint32_t)__cvta_generic_to_shared(stage);

    const int lo = g_rowptr[n0];
    const int hi = g_rowptr[min(n0 + 8, N)];

    float4 acc[8];
#pragma unroll
    for (int m = 0; m < 8; m++) acc[m] = make_float4(0.f, 0.f, 0.f, 0.f);

    // ldmatrix per-lane address: matrix g = lane/8; p = lane%8
    //  g0: edges 0-7  dims +0 | g1: edges 0-7 dims +16B | g2: edges 8-15 +0 | g3: edges 8-15 +16B
    const int eoff   = (lane & 7) + ((lane >> 4) << 3);
    const int dimX   = ((lane >> 3) & 1) * 16;
    const uint32_t lmBase = stageAddr + eoff * STAGE_STRIDE + dimX;

    const int      k0 = (lane & 3) * 2;
    const unsigned nn = lane >> 2;

    for (int e0 = lo; e0 < hi; e0 += 16) {
        // ---- per-edge metadata (lanes mirror edges 0..15) ----
        const int el  = e0 + (lane & 15);
        const int ecc = min(el, hi - 1);
        const int   c = __ldg(cols + ecc);
        const int   r = __ldg(rows + ecc);
        const float v = __ldg(vals + ecc);
        const unsigned relrow = (el < hi) ? (unsigned)(r - n0) : 0xFFu;
        const unsigned vh     = (unsigned)__half_as_ushort(__float2half_rn(v));
        const unsigned rv     = (relrow << 16) | vh;

        // ---- B fragment: B[k][n] = (row_k == n) ? v_k : 0 ----
        const unsigned x0 = __shfl_sync(0xffffffffu, rv, k0);
        const unsigned x1 = __shfl_sync(0xffffffffu, rv, k0 + 1);
        const unsigned x2 = __shfl_sync(0xffffffffu, rv, k0 + 8);
        const unsigned x3 = __shfl_sync(0xffffffffu, rv, k0 + 9);
        const unsigned b0 = ((x0 >> 16) == nn ? (x0 & 0xffffu) : 0u)
                          | ((x1 >> 16) == nn ? (x1 << 16) : 0u);
        const unsigned b1 = ((x2 >> 16) == nn ? (x2 & 0xffffu) : 0u)
                          | ((x3 >> 16) == nn ? (x3 << 16) : 0u);

        // ---- gather 16 rows (256B each) into smem via cp.async ----
        const uint32_t part = (lane & 15) << 4;     // 16B chunk within row
        const uint32_t sbase = stageAddr + part;
#pragma unroll
        for (int i = 0; i < 8; i++) {
            const int e  = i * 2 + (lane >> 4);
            const int ce = __shfl_sync(0xffffffffu, c, e);
            const char* g = (const char*)g_hWh + ((size_t)(unsigned)ce << 8) + part;
            const uint32_t sa = sbase + e * STAGE_STRIDE;
            asm volatile("cp.async.cg.shared.global [%0], [%1], 16;\n"
                         :: "r"(sa), "l"(g));
        }
        asm volatile("cp.async.commit_group;\n" ::);
        asm volatile("cp.async.wait_group 0;\n" ::);
        __syncwarp();

        // ---- 8 M-tiles: ldmatrix.trans + mma ----
#pragma unroll
        for (int m = 0; m < 8; m++) {
            uint32_t a0, a1, a2, a3;
            asm volatile(
                "ldmatrix.sync.aligned.m8n8.x4.trans.shared.b16 {%0,%1,%2,%3}, [%4];\n"
                : "=r"(a0), "=r"(a1), "=r"(a2), "=r"(a3)
                : "r"(lmBase + 32 * m));
            mma16816(acc[m], a0, a1, a2, a3, b0, b1);
        }
        __syncwarp();
    }

    // ---- epilogue: transpose C through smem, add bias, ReLU, write ----
    float* stageF = reinterpret_cast<float*>(stage);   // [node][132 floats]
    const int d0 = lane >> 2;        // dim within tile (row)
    const int u0 = (lane & 3) * 2;   // node (col)
    __syncwarp();
#pragma unroll
    for (int m = 0; m < 8; m++) {
        const int dd = 16 * m + d0;
        stageF[u0 * 132 + dd]             = acc[m].x;
        stageF[(u0 + 1) * 132 + dd]       = acc[m].y;
        stageF[u0 * 132 + dd + 8]         = acc[m].z;
        stageF[(u0 + 1) * 132 + dd + 8]   = acc[m].w;
    }
    __syncwarp();

    const float4 bb = bsm4[lane];
    for (int u = 0; u < nodeEnd; u++) {
        float4 vv = *reinterpret_cast<float4*>(&stageF[u * 132 + lane * 4]);
        vv.x = fmaxf(vv.x + bb.x, 0.f);
        vv.y = fmaxf(vv.y + bb.y, 0.f);
        vv.z = fmaxf(vv.z + bb.z, 0.f);
        vv.w = fmaxf(vv.w + bb.w, 0.f);
        reinterpret_cast<float4*>(out)[(size_t)(n0 + u) * 32 + lane] = vv;
    }
}

// ---------------------------------------------------------------------------
// Inputs (metadata order): edge_rows i32, edge_cols i32, edge_vals f32,
//                          h f32 [N,128], W f32 [128,128], b f32 [128]
// ---------------------------------------------------------------------------
extern "C" void kernel_launch(void* const* d_in, const int* in_sizes, int n_in,
                              void* d_out, int out_size)
{
    const int*   rows = (const int*)  d_in[0];
    const int*   cols = (const int*)  d_in[1];
    const float* vals = (const float*)d_in[2];
    const float* h    = (const float*)d_in[3];
    const float* W    = (const float*)d_in[4];
    const float* b    = (const float*)d_in[5];
    float*       out  = (float*)d_out;

    const int E = in_sizes[0];
    const int N = in_sizes[3] / D;   // 100000

    gemm_hwt_fp16_kernel<<<(N + 127) / 128, 256>>>(h, W, N);
    build_rowptr_kernel<<<(E + 255) / 256, 256>>>(rows, E, N);

    const int nodeGroups = (N + 7) / 8;
    spmm_tc_kernel<<<(nodeGroups + WARPS_PER_BLOCK - 1) / WARPS_PER_BLOCK, 256>>>(
        rows, cols, vals, b, out, N);
}

// round 4
// speedup vs baseline: 1.0437x; 1.0437x over previous
#include <cuda_runtime.h>
#include <cuda_fp16.h>
#include <cstdint>

#define D 128
#define NMAX 100000

// Scratch (device globals -- no allocation allowed):
__device__ __half g_hWh[(size_t)NMAX * D];     // hW = h @ W^T in fp16
__device__ int    g_rowptr[NMAX + 1];

// ---------------------------------------------------------------------------
// mma.sync m16n8k16 fp16 -> fp32
// ---------------------------------------------------------------------------
__device__ __forceinline__ void mma16816(float4& c,
                                         uint32_t a0, uint32_t a1, uint32_t a2, uint32_t a3,
                                         uint32_t b0, uint32_t b1)
{
    asm volatile(
        "mma.sync.aligned.m16n8k16.row.col.f32.f16.f16.f32 "
        "{%0,%1,%2,%3}, {%4,%5,%6,%7}, {%8,%9}, {%0,%1,%2,%3};\n"
        : "+f"(c.x), "+f"(c.y), "+f"(c.z), "+f"(c.w)
        : "r"(a0), "r"(a1), "r"(a2), "r"(a3), "r"(b0), "r"(b1));
}

// ---------------------------------------------------------------------------
// Kernel 1: hW[i][j] = sum_k h[i][k] * W[j][k] via mma (fp16 in, fp32 acc).
// ---------------------------------------------------------------------------
#define KC 64
#define KPAD 72

__global__ __launch_bounds__(256) void gemm_hwt_fp16_kernel(
    const float* __restrict__ h,
    const float* __restrict__ W,
    int N)
{
    __shared__ __half Asm[128][KPAD];
    __shared__ __half Bsm[128][KPAD];

    const int t    = threadIdx.x;
    const int lane = t & 31;
    const int warp = t >> 5;
    const int m0   = blockIdx.x * 128;

    const int qr = lane >> 2;
    const int qc = (lane & 3) * 2;
    const int mrow = warp * 16 + qr;

    float4 acc[16];
#pragma unroll
    for (int j = 0; j < 16; j++) acc[j] = make_float4(0.f, 0.f, 0.f, 0.f);

    for (int kc = 0; kc < 2; kc++) {
#pragma unroll
        for (int it = 0; it < 8; it++) {
            int idx = t + it * 256;
            int row = idx >> 4;
            int q   = idx & 15;
            int gr  = m0 + row;
            float4 v = make_float4(0.f, 0.f, 0.f, 0.f);
            if (gr < N)
                v = reinterpret_cast<const float4*>(h + (size_t)gr * D + kc * KC)[q];
            __half2* dst = reinterpret_cast<__half2*>(&Asm[row][q * 4]);
            dst[0] = __floats2half2_rn(v.x, v.y);
            dst[1] = __floats2half2_rn(v.z, v.w);
        }
#pragma unroll
        for (int it = 0; it < 8; it++) {
            int idx = t + it * 256;
            int row = idx >> 4;
            int q   = idx & 15;
            float4 v = reinterpret_cast<const float4*>(W + (size_t)row * D + kc * KC)[q];
            __half2* dst = reinterpret_cast<__half2*>(&Bsm[row][q * 4]);
            dst[0] = __floats2half2_rn(v.x, v.y);
            dst[1] = __floats2half2_rn(v.z, v.w);
        }
        __syncthreads();

        uint32_t a[4][4];
#pragma unroll
        for (int ks = 0; ks < 4; ks++) {
            int kk = ks * 16;
            a[ks][0] = *reinterpret_cast<const uint32_t*>(&Asm[mrow][kk + qc]);
            a[ks][1] = *reinterpret_cast<const uint32_t*>(&Asm[mrow + 8][kk + qc]);
            a[ks][2] = *reinterpret_cast<const uint32_t*>(&Asm[mrow][kk + 8 + qc]);
            a[ks][3] = *reinterpret_cast<const uint32_t*>(&Asm[mrow + 8][kk + 8 + qc]);
        }

#pragma unroll
        for (int j = 0; j < 16; j++) {
            int n0 = j * 8;
            const __half* brow = &Bsm[n0 + qr][0];
#pragma unroll
            for (int ks = 0; ks < 4; ks++) {
                int kk = ks * 16;
                uint32_t b0 = *reinterpret_cast<const uint32_t*>(brow + kk + qc);
                uint32_t b1 = *reinterpret_cast<const uint32_t*>(brow + kk + 8 + qc);
                mma16816(acc[j], a[ks][0], a[ks][1], a[ks][2], a[ks][3], b0, b1);
            }
        }
        __syncthreads();
    }

    const int r0 = m0 + mrow;
    const int r1 = r0 + 8;
#pragma unroll
    for (int j = 0; j < 16; j++) {
        int col = j * 8 + qc;
        if (r0 < N)
            *reinterpret_cast<__half2*>(&g_hWh[(size_t)r0 * D + col]) =
                __floats2half2_rn(acc[j].x, acc[j].y);
        if (r1 < N)
            *reinterpret_cast<__half2*>(&g_hWh[(size_t)r1 * D + col]) =
                __floats2half2_rn(acc[j].z, acc[j].w);
    }
}

// ---------------------------------------------------------------------------
// Kernel 2: build CSR row pointers from sorted edge_rows. O(E) scatter.
// ---------------------------------------------------------------------------
__global__ __launch_bounds__(256) void build_rowptr_kernel(
    const int* __restrict__ rows, int E, int N)
{
    int e = blockIdx.x * blockDim.x + threadIdx.x;
    if (e >= E) return;
    int r     = rows[e];
    int rprev = (e == 0) ? -1 : rows[e - 1];
    for (int i = rprev + 1; i <= r; i++) g_rowptr[i] = e;
    if (e == E - 1) {
        for (int i = r + 1; i <= N; i++) g_rowptr[i] = E;
    }
}

// ---------------------------------------------------------------------------
// Kernel 3: Pipelined tensor-core SpMM. One warp per 8 consecutive nodes.
// Two-stage double-buffered cp.async: gather chunk i+1 while mma'ing chunk i.
// ---------------------------------------------------------------------------
#define STAGE_STRIDE 272              // 256B row + 16B pad
#define TC_WARPS 4                    // warps per block (keeps static smem < 48KB)

struct ChunkMeta {
    int      c;        // per-lane col (lanes mirror edges 0..15)
    uint32_t b0, b1;   // B fragment for mma
};

__device__ __forceinline__ ChunkMeta load_meta(
    const int* __restrict__ rows, const int* __restrict__ cols,
    const float* __restrict__ vals,
    int e0, int hi, int n0, int lane, int k0, unsigned nn)
{
    ChunkMeta m;
    const int el  = e0 + (lane & 15);
    const int ecc = min(el, hi - 1);
    m.c = __ldg(cols + ecc);
    const int   r = __ldg(rows + ecc);
    const float v = __ldg(vals + ecc);
    const unsigned relrow = (el < hi) ? (unsigned)(r - n0) : 0xFFu;
    const unsigned vh     = (unsigned)__half_as_ushort(__float2half_rn(v));
    const unsigned rv     = (relrow << 16) | vh;

    const unsigned x0 = __shfl_sync(0xffffffffu, rv, k0);
    const unsigned x1 = __shfl_sync(0xffffffffu, rv, k0 + 1);
    const unsigned x2 = __shfl_sync(0xffffffffu, rv, k0 + 8);
    const unsigned x3 = __shfl_sync(0xffffffffu, rv, k0 + 9);
    m.b0 = ((x0 >> 16) == nn ? (x0 & 0xffffu) : 0u)
         | ((x1 >> 16) == nn ? (x1 << 16) : 0u);
    m.b1 = ((x2 >> 16) == nn ? (x2 & 0xffffu) : 0u)
         | ((x3 >> 16) == nn ? (x3 << 16) : 0u);
    return m;
}

__device__ __forceinline__ void issue_gather(uint32_t stAddr, int c, int lane)
{
    const uint32_t part  = (lane & 15) << 4;
    const uint32_t sbase = stAddr + part;
#pragma unroll
    for (int i = 0; i < 8; i++) {
        const int e  = i * 2 + (lane >> 4);
        const int ce = __shfl_sync(0xffffffffu, c, e);
        const char* g = (const char*)g_hWh + ((size_t)(unsigned)ce << 8) + part;
        const uint32_t sa = sbase + e * STAGE_STRIDE;
        asm volatile("cp.async.cg.shared.global [%0], [%1], 16;\n"
                     :: "r"(sa), "l"(g));
    }
}

__global__ __launch_bounds__(TC_WARPS * 32) void spmm_tc_kernel(
    const int*   __restrict__ rows,
    const int*   __restrict__ cols,
    const float* __restrict__ vals,
    const float* __restrict__ b,
    float*       __restrict__ out,
    int N)
{
    __shared__ char   stage_raw[TC_WARPS * 2 * 16 * STAGE_STRIDE];
    __shared__ float4 bsm4[32];

    const int t    = threadIdx.x;
    const int lane = t & 31;
    const int warp = t >> 5;

    if (t < 32) bsm4[t] = reinterpret_cast<const float4*>(b)[t];
    __syncthreads();

    const int gw = blockIdx.x * TC_WARPS + warp;
    const int n0 = gw * 8;
    if (n0 >= N) return;
    const int nodeEnd = min(8, N - n0);

    char* stage = stage_raw + warp * 2 * 16 * STAGE_STRIDE;
    const uint32_t st0 = (uint32_t)__cvta_generic_to_shared(stage);
    const uint32_t stAddr[2] = { st0, st0 + 16 * STAGE_STRIDE };

    const int lo = g_rowptr[n0];
    const int hi = g_rowptr[min(n0 + 8, N)];

    float4 acc[8];
#pragma unroll
    for (int m = 0; m < 8; m++) acc[m] = make_float4(0.f, 0.f, 0.f, 0.f);

    const int      eoff = (lane & 7) + ((lane >> 4) << 3);
    const int      dimX = ((lane >> 3) & 1) * 16;
    const int      k0   = (lane & 3) * 2;
    const unsigned nn   = lane >> 2;

    if (lo < hi) {
        // prologue: stage chunk 0 into buffer 0
        ChunkMeta cur = load_meta(rows, cols, vals, lo, hi, n0, lane, k0, nn);
        issue_gather(stAddr[0], cur.c, lane);
        asm volatile("cp.async.commit_group;\n" ::);

        int s = 0;
        for (int e0 = lo; e0 < hi; e0 += 16) {
            const int  enext   = e0 + 16;
            const bool hasNext = enext < hi;
            ChunkMeta nxt;
            if (hasNext) {
                nxt = load_meta(rows, cols, vals, enext, hi, n0, lane, k0, nn);
                issue_gather(stAddr[s ^ 1], nxt.c, lane);
            }
            asm volatile("cp.async.commit_group;\n" ::);   // possibly empty group
            asm volatile("cp.async.wait_group 1;\n" ::);   // buffer s is ready
            __syncwarp();

            const uint32_t lmb = stAddr[s] + eoff * STAGE_STRIDE + dimX;
#pragma unroll
            for (int m = 0; m < 8; m++) {
                uint32_t a0, a1, a2, a3;
                asm volatile(
                    "ldmatrix.sync.aligned.m8n8.x4.trans.shared.b16 {%0,%1,%2,%3}, [%4];\n"
                    : "=r"(a0), "=r"(a1), "=r"(a2), "=r"(a3)
                    : "r"(lmb + 32 * m));
                mma16816(acc[m], a0, a1, a2, a3, cur.b0, cur.b1);
            }
            __syncwarp();
            cur = nxt;
            s ^= 1;
        }
        asm volatile("cp.async.wait_group 0;\n" ::);
    }

    // ---- epilogue: transpose C through smem, add bias, ReLU, write ----
    float* stageF = reinterpret_cast<float*>(stage);   // [node][132 floats]
    const int d0 = lane >> 2;
    const int u0 = (lane & 3) * 2;
    __syncwarp();
#pragma unroll
    for (int m = 0; m < 8; m++) {
        const int dd = 16 * m + d0;
        stageF[u0 * 132 + dd]           = acc[m].x;
        stageF[(u0 + 1) * 132 + dd]     = acc[m].y;
        stageF[u0 * 132 + dd + 8]       = acc[m].z;
        stageF[(u0 + 1) * 132 + dd + 8] = acc[m].w;
    }
    __syncwarp();

    const float4 bb = bsm4[lane];
    for (int u = 0; u < nodeEnd; u++) {
        float4 vv = *reinterpret_cast<float4*>(&stageF[u * 132 + lane * 4]);
        vv.x = fmaxf(vv.x + bb.x, 0.f);
        vv.y = fmaxf(vv.y + bb.y, 0.f);
        vv.z = fmaxf(vv.z + bb.z, 0.f);
        vv.w = fmaxf(vv.w + bb.w, 0.f);
        reinterpret_cast<float4*>(out)[(size_t)(n0 + u) * 32 + lane] = vv;
    }
}

// ---------------------------------------------------------------------------
// Inputs (metadata order): edge_rows i32, edge_cols i32, edge_vals f32,
//                          h f32 [N,128], W f32 [128,128], b f32 [128]
// ---------------------------------------------------------------------------
extern "C" void kernel_launch(void* const* d_in, const int* in_sizes, int n_in,
                              void* d_out, int out_size)
{
    const int*   rows = (const int*)  d_in[0];
    const int*   cols = (const int*)  d_in[1];
    const float* vals = (const float*)d_in[2];
    const float* h    = (const float*)d_in[3];
    const float* W    = (const float*)d_in[4];
    const float* b    = (const float*)d_in[5];
    float*       out  = (float*)d_out;

    const int E = in_sizes[0];
    const int N = in_sizes[3] / D;   // 100000

    gemm_hwt_fp16_kernel<<<(N + 127) / 128, 256>>>(h, W, N);
    build_rowptr_kernel<<<(E + 255) / 256, 256>>>(rows, E, N);

    const int nodeGroups = (N + 7) / 8;   // 12500
    spmm_tc_kernel<<<(nodeGroups + TC_WARPS - 1) / TC_WARPS, TC_WARPS * 32>>>(
        rows, cols, vals, b, out, N);
}